// round 14
// baseline (speedup 1.0000x reference)
#include <cuda_runtime.h>
#include <cuda_fp16.h>
#include <cstdint>

// ---------------- problem constants ----------------
static const int BSZ   = 64;
static const int SEQ   = 256;
static const int DIM   = 512;
static const int HID   = 512;
static const int DHID  = 1024;
static const int NGATE = 2048;              // 4*HID per direction
static const int MROWS = SEQ * BSZ;         // 16384
static const int NTOT  = 4096;              // both directions' gate cols
static const int CLS   = 5;
static const int NCTA  = 128;               // persistent CTAs (<=148 SMs)
static const int NCTA_DIR = 64;             // CTAs per direction

// ---------------- device scratch ----------------
__device__ __half g_xh [(size_t)MROWS * DIM];      // embeddings fp16, 16 MB
__device__ __half g_wh [(size_t)NTOT * DHID];      // W fp16, 8 MB
__device__ __half g_gx [2L * SEQ * BSZ * NGATE];   // x-projection + bias (fp16)
__device__ __half g_hh [2 * 2 * BSZ * HID];        // [dir][parity][b][k] fp16
__device__ __half g_hist[2L * SEQ * BSZ * HID];    // fp16 history, 33.5 MB
__device__ float  g_pooled[BSZ * HID];
__device__ unsigned g_cnt[2 * SEQ * 32];           // barrier counters, 128B-padded

// ---------------- helpers ----------------
__device__ __forceinline__ uint32_t smem_u32(const void* p) {
    uint32_t a;
    asm("{ .reg .u64 t; cvta.to.shared.u64 t, %1; cvt.u32.u64 %0, t; }" : "=r"(a) : "l"(p));
    return a;
}
#define SWZ128(off) ((off) ^ (((off) >> 3) & 0x70))

#define CP_ASYNC16(sa, gp) \
    asm volatile("cp.async.cg.shared.global [%0], [%1], 16;" :: "r"((uint32_t)(sa)), "l"(gp))
#define CP_COMMIT() asm volatile("cp.async.commit_group;" ::: "memory")
#define CP_WAIT0()  asm volatile("cp.async.wait_group 0;" ::: "memory")
#define CP_WAIT1()  asm volatile("cp.async.wait_group 1;" ::: "memory")

__device__ __forceinline__ void ldsm_x4(uint32_t* r, uint32_t addr) {
    asm volatile("ldmatrix.sync.aligned.m8n8.x4.shared.b16 {%0,%1,%2,%3}, [%4];"
                 : "=r"(r[0]), "=r"(r[1]), "=r"(r[2]), "=r"(r[3]) : "r"(addr));
}
// D(16x8 f32) += A(16x16 f16 row) * B(16x8 f16 col)
__device__ __forceinline__ void mma16816(float* d, const uint32_t* a,
                                         uint32_t b0, uint32_t b1) {
    asm volatile(
        "mma.sync.aligned.m16n8k16.row.col.f32.f16.f16.f32 "
        "{%0,%1,%2,%3},{%4,%5,%6,%7},{%8,%9},{%0,%1,%2,%3};"
        : "+f"(d[0]), "+f"(d[1]), "+f"(d[2]), "+f"(d[3])
        : "r"(a[0]), "r"(a[1]), "r"(a[2]), "r"(a[3]), "r"(b0), "r"(b1));
}

extern __shared__ char dynraw[];

// ---------------- kernel 0: zero h plane + barrier counters ----------------
__global__ void k_zero() {
    int i = blockIdx.x * blockDim.x + threadIdx.x;
    if (i < 2 * 2 * BSZ * HID) g_hh[i] = __float2half(0.0f);
    if (i < 2 * SEQ * 32) g_cnt[i] = 0u;
}

// ---------------- kernel 1: W -> fp16 --------------------------------------
__global__ void k_splitw(const float* __restrict__ fwdW, const float* __restrict__ bwdW) {
    size_t i = (size_t)blockIdx.x * 256 + threadIdx.x;    // over NTOT*DHID
    int n = (int)(i >> 10), k = (int)(i & 1023);
    int dir = n >> 11, ng = n & 2047;
    g_wh[i] = __float2half((dir ? bwdW : fwdW)[(size_t)ng * DHID + k]);
}

// ---------------- kernel 2: embedding gather -> fp16 ------------------------
__global__ void k_gather(const int* __restrict__ x, const float* __restrict__ embed) {
    int sb = blockIdx.x;                    // sb = s*BSZ + b
    int b = sb & (BSZ - 1);
    int s = sb >> 6;
    int tok = x[b * SEQ + s];
    int c = threadIdx.x * 4;
    float4 v = *(const float4*)(embed + (size_t)tok * DIM + c);
    size_t base = (size_t)sb * DIM + c;
    *(__half2*)(g_xh + base)     = __half2{__float2half(v.x), __float2half(v.y)};
    *(__half2*)(g_xh + base + 2) = __half2{__float2half(v.z), __float2half(v.w)};
}

// ---------------- kernel 3: x-proj GEMM (fp16 mma, cp.async 2-stage) --------
// C[m][n] = sum_k xs[m][k]*W[n][k] + bias(n).  Tile M=128, N=128, Kchunk=64.
static const int GSTG = 32768;          // per stage: A 16KB + B 16KB
static const int GEMM_SMEM = 65536;

__global__ void __launch_bounds__(256, 2)
k_gemm_fp16(const float* __restrict__ fwdb, const float* __restrict__ bwdb) {
    const int tid = threadIdx.x, wid = tid >> 5, lane = tid & 31;
    const int m0 = blockIdx.y * 128;
    const int n0 = blockIdx.x * 128;
    const int dir = n0 >> 11, ngbase = n0 & 2047;
    const uint32_t smem = smem_u32(dynraw);

    const int wm = (wid >> 1) * 32;         // warp tile: 32 m x 64 n
    const int wn = (wid & 1) * 64;

    const int lm  = lane & 7;
    const int sel = lane >> 3;
    const int rplus = (sel & 1) * 8;
    const int cplus = (sel >> 1) * 16;      // bytes

    const int srow = tid >> 3, sc16 = tid & 7;

    float acc[2][8][4];
#pragma unroll
    for (int i = 0; i < 2; i++)
#pragma unroll
        for (int j = 0; j < 8; j++)
#pragma unroll
            for (int r = 0; r < 4; r++) acc[i][j][r] = 0.0f;

    auto issue = [&](int kc) {
        const int k0 = kc * 64;
        const uint32_t sbase = smem + (kc & 1) * GSTG;
#pragma unroll
        for (int it = 0; it < 4; it++) {
            int row = srow + it * 32;
            uint32_t off = SWZ128((uint32_t)(row * 128 + sc16 * 16));
            CP_ASYNC16(sbase + off,         g_xh + (size_t)(m0 + row) * DIM + k0 + sc16 * 8);
            CP_ASYNC16(sbase + 16384 + off, g_wh + (size_t)(n0 + row) * DHID + k0 + sc16 * 8);
        }
        CP_COMMIT();
    };

    issue(0);
    for (int kc = 0; kc < 8; kc++) {
        if (kc < 7) { issue(kc + 1); CP_WAIT1(); } else { CP_WAIT0(); }
        __syncthreads();
        const uint32_t abase = smem + (kc & 1) * GSTG;
        const uint32_t bbase = abase + 16384;
#pragma unroll
        for (int ks = 0; ks < 4; ks++) {
            const int kb = ks * 32;
            uint32_t a[2][4];
#pragma unroll
            for (int i = 0; i < 2; i++) {
                uint32_t off = SWZ128((uint32_t)((wm + i * 16 + lm + rplus) * 128 + kb + cplus));
                ldsm_x4(a[i], abase + off);
            }
#pragma unroll
            for (int j = 0; j < 4; j++) {
                uint32_t off = SWZ128((uint32_t)((wn + j * 16 + lm + rplus) * 128 + kb + cplus));
                uint32_t bh[4];
                ldsm_x4(bh, bbase + off);
#pragma unroll
                for (int i = 0; i < 2; i++) {
                    mma16816(acc[i][j * 2],     a[i], bh[0], bh[2]);
                    mma16816(acc[i][j * 2 + 1], a[i], bh[1], bh[3]);
                }
            }
        }
        __syncthreads();
    }

    const float* bv = dir ? bwdb : fwdb;
    const size_t dirbase = (size_t)dir * SEQ * BSZ * NGATE;
#pragma unroll
    for (int i = 0; i < 2; i++) {
        int mr0 = m0 + wm + i * 16 + (lane >> 2);
#pragma unroll
        for (int j = 0; j < 8; j++) {
            int ng = ngbase + wn + j * 8 + 2 * (lane & 3);
            float2 bb = *(const float2*)(bv + ng);
            *(__half2*)(g_gx + dirbase + (size_t)mr0 * NGATE + ng) =
                __floats2half2_rn(acc[i][j][0] + bb.x, acc[i][j][1] + bb.y);
            *(__half2*)(g_gx + dirbase + (size_t)(mr0 + 8) * NGATE + ng) =
                __floats2half2_rn(acc[i][j][2] + bb.x, acc[i][j][3] + bb.y);
        }
    }
}

// ---------------- kernel 4: persistent recurrence (fp16, cp.async staging) --
// 128 CTAs: dir = bid>>6, j0 = (bid&63)*8 -> 32 gate cols x 64 batch, K=512.
// Per-direction release/acquire grid barrier (64 arrivals) + nanosleep backoff.
static const int RW  = 0;               // 8 kc x 32 rows x 128B = 32 KB
static const int RH  = 32768;           // 8 kc x 64 rows x 128B = 64 KB
static const int RSP = 98304;           // 64 x 34 floats exchange
static const int RECUR_SMEM = RSP + BSZ * 34 * 4;   // 107008 B

__global__ void __launch_bounds__(256, 1)
k_recur_mma() {
    const int bid = blockIdx.x;
    const int dir = bid >> 6;
    const int j0 = (bid & 63) * 8;
    const int tid = threadIdx.x, wid = tid >> 5, lane = tid & 31;
    const uint32_t smem = smem_u32(dynraw);

    const int lm  = lane & 7;
    const int sel = lane >> 3;
    const int rplus = (sel & 1) * 8;
    const int cplus = (sel >> 1) * 16;
    const int wm = (wid >> 1) * 16;          // batch tile base
    const int wn = (wid & 1) * 16;           // col tile base
    float* sp = (float*)(dynraw + RSP);

    // ---- preload W slice (k in [512,1024)), SW128 per 64-k chunk ----
#pragma unroll
    for (int it = 0; it < 8; it++) {
        int idx = it * 256 + tid;            // 2048 chunks
        int c = idx >> 6, c16 = idx & 63;
        int kc = c16 >> 3;
        int n = dir * 2048 + (c >> 3) * HID + j0 + (c & 7);
        uint32_t off = (uint32_t)(kc * 4096 + SWZ128(c * 128 + (c16 & 7) * 16));
        *(uint4*)(dynraw + RW + off) = *(const uint4*)(g_wh + (size_t)n * DHID + 512 + c16 * 8);
    }
    __syncthreads();

    for (int t = 0; t < SEQ; t++) {
        const int s = dir ? (SEQ - 1 - t) : t;
        const __half* hp = g_hh + ((size_t)dir * 2 + (t & 1)) * (BSZ * HID);
        __half*       hn = g_hh + ((size_t)dir * 2 + ((t + 1) & 1)) * (BSZ * HID);

        // ---- stage full h plane via cp.async.cg (L2 path; bypasses stale L1) ----
#pragma unroll
        for (int it = 0; it < 16; it++) {
            int idx = it * 256 + tid;
            int b = idx >> 6, c16 = idx & 63;
            int kc = c16 >> 3;
            uint32_t off = (uint32_t)(RH + kc * 8192 + SWZ128(b * 128 + (c16 & 7) * 16));
            CP_ASYNC16(smem + off, hp + (size_t)b * HID + c16 * 8);
        }
        CP_COMMIT();

        // prefetch x-projections while copies are in flight
        size_t gxbase = ((size_t)dir * SEQ + s) * BSZ * NGATE;
        float gxa[2][4];
#pragma unroll
        for (int u = 0; u < 2; u++) {
            int it = tid + u * 256, b = it >> 3, jj = it & 7;
#pragma unroll
            for (int g = 0; g < 4; g++)
                gxa[u][g] = __half2float(g_gx[gxbase + (size_t)b * NGATE + g * HID + j0 + jj]);
        }

        CP_WAIT0();
        __syncthreads();

        float acc[2][4];
#pragma unroll
        for (int j = 0; j < 2; j++)
#pragma unroll
            for (int r = 0; r < 4; r++) acc[j][r] = 0.0f;

#pragma unroll 4
        for (int kc = 0; kc < 8; kc++) {
#pragma unroll
            for (int ks = 0; ks < 4; ks++) {
                const int kb = ks * 32;
                uint32_t ah[4], bh[4];
                uint32_t aoff = (uint32_t)(RH + kc * 8192 +
                                SWZ128((wm + lm + rplus) * 128 + kb + cplus));
                ldsm_x4(ah, smem + aoff);
                uint32_t boff = (uint32_t)(RW + kc * 4096 +
                                SWZ128((wn + lm + rplus) * 128 + kb + cplus));
                ldsm_x4(bh, smem + boff);
                mma16816(acc[0], ah, bh[0], bh[2]);
                mma16816(acc[1], ah, bh[1], bh[3]);
            }
        }

        // ---- exchange preacts via smem ----
#pragma unroll
        for (int j = 0; j < 2; j++) {
            int c = wn + j * 8 + 2 * (lane & 3);
            int b = wm + (lane >> 2);
            *(float2*)(sp + b * 34 + c)       = make_float2(acc[j][0], acc[j][1]);
            *(float2*)(sp + (b + 8) * 34 + c) = make_float2(acc[j][2], acc[j][3]);
        }
        __syncthreads();

        // ---- nonlinearity: 512 (b,jj) items, 2 per thread ----
#pragma unroll
        for (int u = 0; u < 2; u++) {
            int it = tid + u * 256, b = it >> 3, jj = it & 7;
            float f_ = sp[b * 34 + jj]      + gxa[u][0];
            float i_ = sp[b * 34 + 8 + jj]  + gxa[u][1];
            float c_ = sp[b * 34 + 16 + jj] + gxa[u][2];
            float o_ = sp[b * 34 + 24 + jj] + gxa[u][3];
            float fg = 1.0f / (1.0f + __expf(-f_));
            float ig = 1.0f / (1.0f + __expf(-i_));
            float ct = tanhf(c_);
            float og = 1.0f / (1.0f + __expf(-o_));
            float hh = og * tanhf((fg + ig) * ct);      // faithful: c_prev unused
            int j = j0 + jj;
            __half hq = __float2half(hh);
            g_hist[(((size_t)dir * SEQ + s) * BSZ + b) * HID + j] = hq;
            hn[(size_t)b * HID + j] = hq;
        }

        // ---- per-direction grid barrier: release add, acquire poll + sleep ----
        __syncthreads();
        if (tid == 0) {
            unsigned* cnt = &g_cnt[(dir * SEQ + t) * 32];
            asm volatile("red.release.gpu.global.add.u32 [%0], %1;"
                         :: "l"(cnt), "r"(1u) : "memory");
            unsigned v;
            asm volatile("ld.acquire.gpu.global.u32 %0, [%1];" : "=r"(v) : "l"(cnt));
            while (v < (unsigned)NCTA_DIR) {
                asm volatile("nanosleep.u32 200;");
                asm volatile("ld.acquire.gpu.global.u32 %0, [%1];" : "=r"(v) : "l"(cnt));
            }
        }
        __syncthreads();
    }
}

// ---------------- kernel 5: pooled = tanh(max_s (hf*hb))  [tanh monotonic] --
__global__ void k_pool() {
    int b = blockIdx.y;
    int h2 = blockIdx.x * 128 + threadIdx.x;     // half2 index, 0..255
    const __half2* pf = (const __half2*)g_hist + (size_t)b * (HID / 2) + h2;
    const __half2* pb = pf + (size_t)SEQ * BSZ * (HID / 2);
    float2 m = make_float2(-1e30f, -1e30f);
#pragma unroll 4
    for (int s = 0; s < SEQ; s++) {
        float2 a = __half22float2(pf[(size_t)s * BSZ * (HID / 2)]);
        float2 c = __half22float2(pb[(size_t)s * BSZ * (HID / 2)]);
        m.x = fmaxf(m.x, a.x * c.x);
        m.y = fmaxf(m.y, a.y * c.y);
    }
    *(float2*)(g_pooled + b * HID + 2 * h2) = make_float2(tanhf(m.x), tanhf(m.y));
}

// ---------------- kernel 6: out = pooled @ Wout^T + bout ----------------
__global__ void k_out(const float* __restrict__ Wout, const float* __restrict__ bout,
                      float* __restrict__ out) {
    int b = blockIdx.x;
    int c = threadIdx.x >> 5;
    int lane = threadIdx.x & 31;
    float sum = 0.0f;
    for (int h = lane; h < HID; h += 32)
        sum += g_pooled[b * HID + h] * Wout[c * HID + h];
#pragma unroll
    for (int off = 16; off; off >>= 1)
        sum += __shfl_down_sync(0xffffffffu, sum, off);
    if (lane == 0) out[b * CLS + c] = sum + bout[c];
}

// ---------------- launcher ----------------
extern "C" void kernel_launch(void* const* d_in, const int* in_sizes, int n_in,
                              void* d_out, int out_size) {
    const int*   x     = (const int*)d_in[0];
    const float* embed = (const float*)d_in[1];
    const float* fwdW  = (const float*)d_in[2];
    const float* fwdb  = (const float*)d_in[3];
    const float* bwdW  = (const float*)d_in[4];
    const float* bwdb  = (const float*)d_in[5];
    const float* Wout  = (const float*)d_in[6];
    const float* bout  = (const float*)d_in[7];
    float* out = (float*)d_out;

    cudaFuncSetAttribute(k_gemm_fp16, cudaFuncAttributeMaxDynamicSharedMemorySize, GEMM_SMEM);
    cudaFuncSetAttribute(k_recur_mma, cudaFuncAttributeMaxDynamicSharedMemorySize, RECUR_SMEM);

    k_zero<<<(2 * SEQ * 32 + 255) / 256 > 512 ? (2 * SEQ * 32 + 255) / 256 : 512, 256>>>();
    k_splitw<<<NTOT * DHID / 256, 256>>>(fwdW, bwdW);
    k_gather<<<MROWS, 128>>>(x, embed);
    k_gemm_fp16<<<dim3(NTOT / 128, MROWS / 128), 256, GEMM_SMEM>>>(fwdb, bwdb);
    k_recur_mma<<<NCTA, 256, RECUR_SMEM>>>();
    k_pool<<<dim3(HID / 256, BSZ), 128>>>();
    k_out<<<BSZ, CLS * 32>>>(Wout, bout, out);
}